// round 1
// baseline (speedup 1.0000x reference)
#include <cuda_runtime.h>
#include <math.h>

#define BATCH 4
#define CIN   128
#define NSEQ  4096
#define DK    64
#define DV    128

#define BM 64
#define BN 32

// Scratch for projected Q/K/V (transposed layouts for attention)
static __device__ float g_Qt[BATCH * NSEQ * DK];   // [b][n][k]
static __device__ float g_Kt[BATCH * NSEQ * DK];   // [b][m][k]
static __device__ float g_Vt[BATCH * NSEQ * DV];   // [b][m][o]

// ---------------------------------------------------------------------------
// Projection kernel: Q = Wq @ x, K = Wk @ x, V = Wv @ x  (1x1 convs)
// Block handles one (b, 32-wide n tile). 256 threads = 256 output channels
// (64 Q + 64 K + 128 V). x tile staged in smem, W rows streamed from L1/L2.
// ---------------------------------------------------------------------------
__global__ __launch_bounds__(256) void proj_kernel(
    const float* __restrict__ x,
    const float* __restrict__ Wq,
    const float* __restrict__ Wk,
    const float* __restrict__ Wv)
{
    __shared__ float xs[CIN][32];

    int b  = blockIdx.x >> 7;          // / (NSEQ/32)
    int n0 = (blockIdx.x & 127) << 5;  // * 32
    int tid = threadIdx.x;

    for (int idx = tid; idx < CIN * 32; idx += 256) {
        int i = idx >> 5, j = idx & 31;
        xs[i][j] = x[(b * CIN + i) * NSEQ + n0 + j];
    }
    __syncthreads();

    int c = tid;
    const float* Wrow;
    float* dst;
    int dstride;
    if (c < 64)       { Wrow = Wq + c * CIN;         dst = g_Qt + (b * NSEQ + n0) * DK + c;         dstride = DK; }
    else if (c < 128) { Wrow = Wk + (c - 64) * CIN;  dst = g_Kt + (b * NSEQ + n0) * DK + (c - 64);  dstride = DK; }
    else              { Wrow = Wv + (c - 128) * CIN; dst = g_Vt + (b * NSEQ + n0) * DV + (c - 128); dstride = DV; }

    float acc[32];
#pragma unroll
    for (int j = 0; j < 32; j++) acc[j] = 0.f;

#pragma unroll 4
    for (int i = 0; i < CIN; i++) {
        float w = Wrow[i];
        const float4* xr = (const float4*)xs[i];
#pragma unroll
        for (int jj = 0; jj < 8; jj++) {
            float4 v = xr[jj];
            acc[jj * 4 + 0] += w * v.x;
            acc[jj * 4 + 1] += w * v.y;
            acc[jj * 4 + 2] += w * v.z;
            acc[jj * 4 + 3] += w * v.w;
        }
    }
#pragma unroll
    for (int j = 0; j < 32; j++) dst[j * dstride] = acc[j];
}

// ---------------------------------------------------------------------------
// Flash attention kernel (fp32, CUDA cores).
// Grid: BATCH * (NSEQ/BM) blocks, 256 threads, 2 CTAs/SM.
// Per key tile: GEMM1 (S = Q K^T, 64x32x64) -> smem -> online softmax
// (2 threads/row) -> rescale accs -> GEMM2 (O += P V, 64x128x32).
// ---------------------------------------------------------------------------
struct __align__(16) AttnSmem {
    float Qs[BM][DK + 4];   // padded: row stride 68 floats
    float Ks[BN][DK + 4];   // padded: row stride 68 floats
    float Vs[BN][DV + 4];   // padded: row stride 132 floats
    float Ps[BM][BN + 1];   // padded: row stride 33 floats (scalar access only)
    float scale_s[BM];
    float l_s[BM];
};

#define ATTN_SMEM_BYTES ((int)sizeof(AttnSmem))

__global__ __launch_bounds__(256, 2) void attn_kernel(float* __restrict__ out)
{
    extern __shared__ char smem_raw[];
    AttnSmem* S = (AttnSmem*)smem_raw;

    int b  = blockIdx.x >> 6;          // / (NSEQ/BM)
    int n0 = (blockIdx.x & 63) * BM;
    int tid = threadIdx.x;
    int ty = tid >> 4;   // 0..15 -> query rows ty*4 .. ty*4+3
    int tx = tid & 15;   // 0..15

    // Load Q tile (row-padded)
    {
        const float4* Qg4 = (const float4*)(g_Qt + (b * NSEQ + n0) * DK);
        for (int idx = tid; idx < BM * DK / 4; idx += 256) {
            int row = idx >> 4, c4 = idx & 15;
            *(float4*)&S->Qs[row][c4 * 4] = Qg4[idx];
        }
    }

    float acc[4][8];
#pragma unroll
    for (int i = 0; i < 4; i++)
#pragma unroll
        for (int j = 0; j < 8; j++) acc[i][j] = 0.f;

    const float NEG_INF = __int_as_float(0xff800000);
    float m_r = NEG_INF, l_r = 0.f;   // valid for tid < 128 (2 threads per row)

    const float* Kg = g_Kt + b * NSEQ * DK;
    const float* Vg = g_Vt + b * NSEQ * DV;

    for (int kt = 0; kt < NSEQ / BN; kt++) {
        __syncthreads();   // prior iteration's GEMM2 done reading Vs/Ps (also covers Q load, iter 0)

        // Load K and V tiles (coalesced float4, into padded rows)
        {
            const float4* Ksrc = (const float4*)(Kg + kt * BN * DK);
            for (int idx = tid; idx < BN * DK / 4; idx += 256) {
                int row = idx >> 4, c4 = idx & 15;
                *(float4*)&S->Ks[row][c4 * 4] = Ksrc[idx];
            }
            const float4* Vsrc = (const float4*)(Vg + kt * BN * DV);
            for (int idx = tid; idx < BN * DV / 4; idx += 256) {
                int row = idx >> 5, c4 = idx & 31;
                *(float4*)&S->Vs[row][c4 * 4] = Vsrc[idx];
            }
        }
        __syncthreads();

        // GEMM1: S[r][c] = sum_k Q[r][k] K[c][k]; cols {tx, tx+16}
        {
            float sres[4][2];
#pragma unroll
            for (int i = 0; i < 4; i++) { sres[i][0] = 0.f; sres[i][1] = 0.f; }
#pragma unroll
            for (int k = 0; k < DK; k += 4) {
                float4 kb0 = *(const float4*)&S->Ks[tx][k];
                float4 kb1 = *(const float4*)&S->Ks[tx + 16][k];
#pragma unroll
                for (int i = 0; i < 4; i++) {
                    float4 q = *(const float4*)&S->Qs[ty * 4 + i][k];
                    sres[i][0] += q.x * kb0.x + q.y * kb0.y + q.z * kb0.z + q.w * kb0.w;
                    sres[i][1] += q.x * kb1.x + q.y * kb1.y + q.z * kb1.z + q.w * kb1.w;
                }
            }
#pragma unroll
            for (int i = 0; i < 4; i++) {
                S->Ps[ty * 4 + i][tx]      = sres[i][0];
                S->Ps[ty * 4 + i][tx + 16] = sres[i][1];
            }
        }
        __syncthreads();

        // Online softmax: 2 threads per row, 16 cols each, shfl-combine
        if (tid < 2 * BM) {
            int r = tid >> 1;
            int h = tid & 1;
            int j0 = h * 16;
            float tmax = NEG_INF;
#pragma unroll
            for (int j = 0; j < 16; j++) tmax = fmaxf(tmax, S->Ps[r][j0 + j]);
            tmax = fmaxf(tmax, __shfl_xor_sync(0xFFFFFFFFu, tmax, 1));
            float new_m = fmaxf(m_r, tmax);
            float corr  = __expf(m_r - new_m);
            float sum = 0.f;
#pragma unroll
            for (int j = 0; j < 16; j++) {
                float p = __expf(S->Ps[r][j0 + j] - new_m);
                S->Ps[r][j0 + j] = p;
                sum += p;
            }
            sum += __shfl_xor_sync(0xFFFFFFFFu, sum, 1);
            l_r = l_r * corr + sum;
            m_r = new_m;
            if (h == 0) S->scale_s[r] = corr;
        }
        __syncthreads();

        // Rescale accumulators + GEMM2: O += P V.  Cols {tx*4..+3, 64+tx*4..+3}
#pragma unroll
        for (int i = 0; i < 4; i++) {
            float c = S->scale_s[ty * 4 + i];
#pragma unroll
            for (int j = 0; j < 8; j++) acc[i][j] *= c;
        }
#pragma unroll 4
        for (int j = 0; j < BN; j++) {
            float4 v0 = *(const float4*)&S->Vs[j][tx * 4];
            float4 v1 = *(const float4*)&S->Vs[j][64 + tx * 4];
            float p[4];
#pragma unroll
            for (int i = 0; i < 4; i++) p[i] = S->Ps[ty * 4 + i][j];
#pragma unroll
            for (int i = 0; i < 4; i++) {
                acc[i][0] += p[i] * v0.x;
                acc[i][1] += p[i] * v0.y;
                acc[i][2] += p[i] * v0.z;
                acc[i][3] += p[i] * v0.w;
                acc[i][4] += p[i] * v1.x;
                acc[i][5] += p[i] * v1.y;
                acc[i][6] += p[i] * v1.z;
                acc[i][7] += p[i] * v1.w;
            }
        }
    }

    if (tid < 2 * BM && (tid & 1) == 0) S->l_s[tid >> 1] = l_r;
    __syncthreads();

    // Epilogue: out[b][o][n] = acc / l
#pragma unroll
    for (int i = 0; i < 4; i++) {
        int n = n0 + ty * 4 + i;
        float inv = 1.f / S->l_s[ty * 4 + i];
#pragma unroll
        for (int j = 0; j < 4; j++) {
            out[(b * DV + tx * 4 + j) * NSEQ + n]      = acc[i][j] * inv;
            out[(b * DV + 64 + tx * 4 + j) * NSEQ + n] = acc[i][j + 4] * inv;
        }
    }
}

// ---------------------------------------------------------------------------
extern "C" void kernel_launch(void* const* d_in, const int* in_sizes, int n_in,
                              void* d_out, int out_size)
{
    const float* x  = (const float*)d_in[0];
    const float* Wq = (const float*)d_in[1];
    const float* Wk = (const float*)d_in[2];
    const float* Wv = (const float*)d_in[3];
    float* out = (float*)d_out;

    cudaFuncSetAttribute(attn_kernel, cudaFuncAttributeMaxDynamicSharedMemorySize,
                         ATTN_SMEM_BYTES);

    proj_kernel<<<BATCH * (NSEQ / 32), 256>>>(x, Wq, Wk, Wv);
    attn_kernel<<<BATCH * (NSEQ / BM), 256, ATTN_SMEM_BYTES>>>(out);
}

// round 3
// speedup vs baseline: 2.9840x; 2.9840x over previous
#include <cuda_runtime.h>
#include <cuda_bf16.h>
#include <stdint.h>

#define BATCH 4
#define CIN   128
#define NSEQ  4096
#define DK    64
#define DV    128
#define BM    128
#define BN    64
#define NITER (NSEQ / BN)

// bf16 hi/lo split scratch
static __device__ __align__(128) __nv_bfloat16 g_Qh[BATCH * NSEQ * DK];  // [b][n][k]
static __device__ __align__(128) __nv_bfloat16 g_Ql[BATCH * NSEQ * DK];
static __device__ __align__(128) __nv_bfloat16 g_Kh[BATCH * NSEQ * DK];  // [b][m][k]
static __device__ __align__(128) __nv_bfloat16 g_Kl[BATCH * NSEQ * DK];
static __device__ __align__(128) __nv_bfloat16 g_Vh[BATCH * NSEQ * DV];  // [b][m][o]
static __device__ __align__(128) __nv_bfloat16 g_Vl[BATCH * NSEQ * DV];

__device__ __forceinline__ uint32_t smem_u32(const void* p) {
    uint32_t a;
    asm("{ .reg .u64 t; cvta.to.shared.u64 t, %1; cvt.u32.u64 %0, t; }" : "=r"(a) : "l"(p));
    return a;
}
#define CP_ASYNC16(dst, src) \
    asm volatile("cp.async.cg.shared.global [%0], [%1], 16;" :: "r"(dst), "l"(src) : "memory")
#define CP_COMMIT() asm volatile("cp.async.commit_group;" ::: "memory")
#define CP_WAIT0()  asm volatile("cp.async.wait_group 0;" ::: "memory")

__device__ __forceinline__ void ldsm4(uint32_t* r, uint32_t a) {
    asm volatile("ldmatrix.sync.aligned.m8n8.x4.shared.b16 {%0,%1,%2,%3}, [%4];"
        : "=r"(r[0]), "=r"(r[1]), "=r"(r[2]), "=r"(r[3]) : "r"(a));
}
__device__ __forceinline__ void ldsm4t(uint32_t* r, uint32_t a) {
    asm volatile("ldmatrix.sync.aligned.m8n8.x4.trans.shared.b16 {%0,%1,%2,%3}, [%4];"
        : "=r"(r[0]), "=r"(r[1]), "=r"(r[2]), "=r"(r[3]) : "r"(a));
}
__device__ __forceinline__ void mma16816(float* d, const uint32_t* a, uint32_t b0, uint32_t b1) {
    asm volatile("mma.sync.aligned.m16n8k16.row.col.f32.bf16.bf16.f32 "
        "{%0,%1,%2,%3}, {%4,%5,%6,%7}, {%8,%9}, {%0,%1,%2,%3};"
        : "+f"(d[0]), "+f"(d[1]), "+f"(d[2]), "+f"(d[3])
        : "r"(a[0]), "r"(a[1]), "r"(a[2]), "r"(a[3]), "r"(b0), "r"(b1));
}
__device__ __forceinline__ uint32_t packbf(float hi, float lo) {
    uint32_t r;
    asm("cvt.rn.bf16x2.f32 %0, %1, %2;" : "=r"(r) : "f"(hi), "f"(lo));
    return r;
}

// ---------------------------------------------------------------------------
// Projection: fp32 1x1 convs -> bf16 hi/lo splits.
// ---------------------------------------------------------------------------
__global__ __launch_bounds__(256) void proj_kernel(
    const float* __restrict__ x, const float* __restrict__ Wq,
    const float* __restrict__ Wk, const float* __restrict__ Wv)
{
    __shared__ float xs[CIN][32];
    int b  = blockIdx.x >> 7;
    int n0 = (blockIdx.x & 127) << 5;
    int tid = threadIdx.x;

    for (int idx = tid; idx < CIN * 32; idx += 256) {
        int i = idx >> 5, j = idx & 31;
        xs[i][j] = x[(b * CIN + i) * NSEQ + n0 + j];
    }
    __syncthreads();

    int c = tid;
    const float* Wrow = (c < 64) ? (Wq + c * CIN)
                     : (c < 128) ? (Wk + (c - 64) * CIN)
                                 : (Wv + (c - 128) * CIN);
    float acc[32];
#pragma unroll
    for (int j = 0; j < 32; j++) acc[j] = 0.f;
#pragma unroll 4
    for (int i = 0; i < CIN; i++) {
        float w = Wrow[i];
        const float4* xr = (const float4*)xs[i];
#pragma unroll
        for (int jj = 0; jj < 8; jj++) {
            float4 v = xr[jj];
            acc[jj * 4 + 0] += w * v.x;
            acc[jj * 4 + 1] += w * v.y;
            acc[jj * 4 + 2] += w * v.z;
            acc[jj * 4 + 3] += w * v.w;
        }
    }
    if (c < 128) {
        __nv_bfloat16* dh = (c < 64) ? g_Qh : g_Kh;
        __nv_bfloat16* dl = (c < 64) ? g_Ql : g_Kl;
        int cc = c & 63;
#pragma unroll
        for (int j = 0; j < 32; j++) {
            float v = acc[j];
            __nv_bfloat16 h = __float2bfloat16(v);
            __nv_bfloat16 l = __float2bfloat16(v - __bfloat162float(h));
            size_t o = ((size_t)(b * NSEQ + n0 + j)) * DK + cc;
            dh[o] = h; dl[o] = l;
        }
    } else {
        int oo = c - 128;
        size_t base = ((size_t)(b * NSEQ + n0)) * DV + oo;
#pragma unroll
        for (int j = 0; j < 32; j++) {
            float v = acc[j];
            __nv_bfloat16 h = __float2bfloat16(v);
            __nv_bfloat16 l = __float2bfloat16(v - __bfloat162float(h));
            g_Vh[base + (size_t)j * DV] = h;
            g_Vl[base + (size_t)j * DV] = l;
        }
    }
}

// ---------------------------------------------------------------------------
// FA2 attention, mma.sync bf16 hi/lo split. 8 warps x 16 query rows = BM=128.
// smem: QH 0 | QL 16K | KH 32K | KL 40K | VH0 48K | VH1 56K | VL0 64K | VL1 72K
// ---------------------------------------------------------------------------
#define SM_QH 0
#define SM_QL 16384
#define SM_KH 32768
#define SM_KL 40960
#define SM_VH 49152
#define SM_VL 65536
#define SMEM_BYTES 81920

__global__ __launch_bounds__(256, 1) void attn_kernel(float* __restrict__ out)
{
    extern __shared__ char raw[];
    uint32_t sb = smem_u32(raw);

    int tid = threadIdx.x, w = tid >> 5, lane = tid & 31;
    int b  = blockIdx.x >> 5;
    int q0 = (blockIdx.x & 31) * BM;

    // per-lane ldmatrix address precompute (SW128: chunk ^= row&7)
    uint32_t xm = (lane & 7) << 4;
    uint32_t qrow = 16 * w + (lane & 15);
    uint32_t qc   = (lane >> 4) << 4;
    uint32_t aQH = sb + SM_QH + qrow * 128;
    uint32_t aQL = sb + SM_QL + qrow * 128;
    uint32_t krow = (lane & 7) + ((lane >> 4) << 3);
    uint32_t kc   = ((lane >> 3) & 1) << 4;
    uint32_t aKH = sb + SM_KH + krow * 128;
    uint32_t aKL = sb + SM_KL + krow * 128;
    uint32_t vrow = (lane & 7) + (((lane >> 3) & 1) << 3);
    uint32_t vc   = (lane >> 4) << 4;
    uint32_t aVH = sb + SM_VH + vrow * 128;
    uint32_t aVL = sb + SM_VL + vrow * 128;

    const char* gQh = (const char*)g_Qh + ((size_t)(b * NSEQ + q0)) * 128;
    const char* gQl = (const char*)g_Ql + ((size_t)(b * NSEQ + q0)) * 128;
    const char* gKh = (const char*)g_Kh + ((size_t)b * NSEQ) * 128;
    const char* gKl = (const char*)g_Kl + ((size_t)b * NSEQ) * 128;
    const char* gVh = (const char*)g_Vh + ((size_t)b * NSEQ) * 256;
    const char* gVl = (const char*)g_Vl + ((size_t)b * NSEQ) * 256;

    // Q tiles (once)
    for (int i = tid; i < 1024; i += 256) {
        uint32_t r = i >> 3, c = i & 7;
        uint32_t so = r * 128 + ((c ^ (r & 7)) << 4);
        size_t go = (size_t)r * 128 + c * 16;
        CP_ASYNC16(sb + SM_QH + so, gQh + go);
        CP_ASYNC16(sb + SM_QL + so, gQl + go);
    }
    CP_COMMIT();

    uint32_t QHf[4][4], QLf[4][4];
    float Of[16][4];
#pragma unroll
    for (int t = 0; t < 16; t++)
#pragma unroll
        for (int j = 0; j < 4; j++) Of[t][j] = 0.f;
    float m0 = -1e30f, m1 = -1e30f, l0 = 0.f, l1 = 0.f;

    for (int kt = 0; kt < NITER; kt++) {
        if (kt) __syncthreads();
        // load K/V tiles for this iteration
        for (int i = tid; i < 512; i += 256) {
            uint32_t r = i >> 3, c = i & 7;
            uint32_t so = r * 128 + ((c ^ (r & 7)) << 4);
            size_t ko = (size_t)(kt * BN + r) * 128 + c * 16;
            CP_ASYNC16(sb + SM_KH + so, gKh + ko);
            CP_ASYNC16(sb + SM_KL + so, gKl + ko);
            size_t vo = (size_t)(kt * BN + r) * 256 + c * 16;
            CP_ASYNC16(sb + SM_VH + so,        gVh + vo);
            CP_ASYNC16(sb + SM_VH + 8192 + so, gVh + vo + 128);
            CP_ASYNC16(sb + SM_VL + so,        gVl + vo);
            CP_ASYNC16(sb + SM_VL + 8192 + so, gVl + vo + 128);
        }
        CP_COMMIT();
        CP_WAIT0();
        __syncthreads();

        if (kt == 0) {
#pragma unroll
            for (int ks = 0; ks < 4; ks++) {
                uint32_t cc = (ks * 32 + qc) ^ xm;
                ldsm4(QHf[ks], aQH + cc);
                ldsm4(QLf[ks], aQL + cc);
            }
        }

        // ---- GEMM1: S = Qh*Kh + Ql*Kh + Qh*Kl ----
        float Sx[8][4];
#pragma unroll
        for (int t = 0; t < 8; t++)
#pragma unroll
            for (int j = 0; j < 4; j++) Sx[t][j] = 0.f;
#pragma unroll
        for (int tp = 0; tp < 4; tp++) {
#pragma unroll
            for (int ks = 0; ks < 4; ks++) {
                uint32_t cc = (ks * 32 + kc) ^ xm;
                uint32_t kh[4], kl[4];
                ldsm4(kh, aKH + tp * 2048 + cc);
                ldsm4(kl, aKL + tp * 2048 + cc);
                mma16816(Sx[2 * tp],     QHf[ks], kh[0], kh[1]);
                mma16816(Sx[2 * tp + 1], QHf[ks], kh[2], kh[3]);
                mma16816(Sx[2 * tp],     QLf[ks], kh[0], kh[1]);
                mma16816(Sx[2 * tp + 1], QLf[ks], kh[2], kh[3]);
                mma16816(Sx[2 * tp],     QHf[ks], kl[0], kl[1]);
                mma16816(Sx[2 * tp + 1], QHf[ks], kl[2], kl[3]);
            }
        }

        // ---- online softmax (registers only) ----
        float mt0 = -1e30f, mt1 = -1e30f;
#pragma unroll
        for (int t = 0; t < 8; t++) {
            mt0 = fmaxf(mt0, fmaxf(Sx[t][0], Sx[t][1]));
            mt1 = fmaxf(mt1, fmaxf(Sx[t][2], Sx[t][3]));
        }
        mt0 = fmaxf(mt0, __shfl_xor_sync(0xffffffffu, mt0, 1));
        mt0 = fmaxf(mt0, __shfl_xor_sync(0xffffffffu, mt0, 2));
        mt1 = fmaxf(mt1, __shfl_xor_sync(0xffffffffu, mt1, 1));
        mt1 = fmaxf(mt1, __shfl_xor_sync(0xffffffffu, mt1, 2));
        float n0v = fmaxf(m0, mt0), n1v = fmaxf(m1, mt1);
        float c0 = __expf(m0 - n0v), c1 = __expf(m1 - n1v);
        m0 = n0v; m1 = n1v;
        l0 *= c0; l1 *= c1;
#pragma unroll
        for (int t = 0; t < 16; t++) {
            Of[t][0] *= c0; Of[t][1] *= c0;
            Of[t][2] *= c1; Of[t][3] *= c1;
        }
        uint32_t PH[8][2], PL[8][2];
#pragma unroll
        for (int t = 0; t < 8; t++) {
            float p0 = __expf(Sx[t][0] - m0), p1 = __expf(Sx[t][1] - m0);
            float p2 = __expf(Sx[t][2] - m1), p3 = __expf(Sx[t][3] - m1);
            l0 += p0 + p1; l1 += p2 + p3;
            uint32_t h01 = packbf(p1, p0);
            uint32_t h23 = packbf(p3, p2);
            PH[t][0] = h01; PH[t][1] = h23;
            float r0 = p0 - __uint_as_float(h01 << 16);
            float r1 = p1 - __uint_as_float(h01 & 0xffff0000u);
            float r2 = p2 - __uint_as_float(h23 << 16);
            float r3 = p3 - __uint_as_float(h23 & 0xffff0000u);
            PL[t][0] = packbf(r1, r0);
            PL[t][1] = packbf(r3, r2);
        }

        // ---- GEMM2: O += Ph*Vh + Pl*Vh + Ph*Vl ----
#pragma unroll
        for (int hp = 0; hp < 2; hp++) {
#pragma unroll
            for (int tp2 = 0; tp2 < 4; tp2++) {
#pragma unroll
                for (int ks = 0; ks < 4; ks++) {
                    uint32_t cc = (tp2 * 32 + vc) ^ xm;
                    uint32_t vh[4], vl[4];
                    ldsm4t(vh, aVH + hp * 8192 + ks * 2048 + cc);
                    ldsm4t(vl, aVL + hp * 8192 + ks * 2048 + cc);
                    int t0 = hp * 8 + tp2 * 2, t1 = t0 + 1;
                    uint32_t aH[4] = { PH[2 * ks][0], PH[2 * ks][1], PH[2 * ks + 1][0], PH[2 * ks + 1][1] };
                    uint32_t aL[4] = { PL[2 * ks][0], PL[2 * ks][1], PL[2 * ks + 1][0], PL[2 * ks + 1][1] };
                    mma16816(Of[t0], aH, vh[0], vh[1]);
                    mma16816(Of[t1], aH, vh[2], vh[3]);
                    mma16816(Of[t0], aL, vh[0], vh[1]);
                    mma16816(Of[t1], aL, vh[2], vh[3]);
                    mma16816(Of[t0], aH, vl[0], vl[1]);
                    mma16816(Of[t1], aH, vl[2], vl[3]);
                }
            }
        }
    }

    // ---- epilogue: normalize, transpose via smem, coalesced store ----
    l0 += __shfl_xor_sync(0xffffffffu, l0, 1);
    l0 += __shfl_xor_sync(0xffffffffu, l0, 2);
    l1 += __shfl_xor_sync(0xffffffffu, l1, 1);
    l1 += __shfl_xor_sync(0xffffffffu, l1, 2);
    float inv0 = 1.f / l0, inv1 = 1.f / l1;

    __syncthreads();
    float* Os = (float*)raw;   // [128][129]
    int rowA = 16 * w + (lane >> 2);
    int rowB = rowA + 8;
#pragma unroll
    for (int t = 0; t < 16; t++) {
        int ch = t * 8 + (lane & 3) * 2;
        Os[rowA * 129 + ch]     = Of[t][0] * inv0;
        Os[rowA * 129 + ch + 1] = Of[t][1] * inv0;
        Os[rowB * 129 + ch]     = Of[t][2] * inv1;
        Os[rowB * 129 + ch + 1] = Of[t][3] * inv1;
    }
    __syncthreads();

    int nn = tid & 127;
    int hf = tid >> 7;
    const float* Or = Os + nn * 129 + hf * 64;
    float* op = out + ((size_t)b * DV + hf * 64) * NSEQ + q0 + nn;
#pragma unroll 8
    for (int c2 = 0; c2 < 64; c2++) op[(size_t)c2 * NSEQ] = Or[c2];
}

// ---------------------------------------------------------------------------
extern "C" void kernel_launch(void* const* d_in, const int* in_sizes, int n_in,
                              void* d_out, int out_size)
{
    const float* x  = (const float*)d_in[0];
    const float* Wq = (const float*)d_in[1];
    const float* Wk = (const float*)d_in[2];
    const float* Wv = (const float*)d_in[3];
    float* out = (float*)d_out;

    cudaFuncSetAttribute(attn_kernel, cudaFuncAttributeMaxDynamicSharedMemorySize,
                         SMEM_BYTES);

    proj_kernel<<<BATCH * (NSEQ / 32), 256>>>(x, Wq, Wk, Wv);
    attn_kernel<<<BATCH * (NSEQ / BM), 256, SMEM_BYTES>>>(out);
}

// round 4
// speedup vs baseline: 3.2616x; 1.0930x over previous
#include <cuda_runtime.h>
#include <cuda_bf16.h>
#include <stdint.h>

#define BATCH 4
#define CIN   128
#define NSEQ  4096
#define DK    64
#define DV    128
#define BM    64
#define BN    64
#define NITER (NSEQ / BN)

// bf16 hi/lo split scratch
static __device__ __align__(128) __nv_bfloat16 g_Qh[BATCH * NSEQ * DK];  // [b][n][k]
static __device__ __align__(128) __nv_bfloat16 g_Ql[BATCH * NSEQ * DK];
static __device__ __align__(128) __nv_bfloat16 g_Kh[BATCH * NSEQ * DK];  // [b][m][k]
static __device__ __align__(128) __nv_bfloat16 g_Kl[BATCH * NSEQ * DK];
static __device__ __align__(128) __nv_bfloat16 g_Vh[BATCH * NSEQ * DV];  // [b][m][o]
static __device__ __align__(128) __nv_bfloat16 g_Vl[BATCH * NSEQ * DV];

__device__ __forceinline__ uint32_t smem_u32(const void* p) {
    uint32_t a;
    asm("{ .reg .u64 t; cvta.to.shared.u64 t, %1; cvt.u32.u64 %0, t; }" : "=r"(a) : "l"(p));
    return a;
}
#define CP_ASYNC16(dst, src) \
    asm volatile("cp.async.cg.shared.global [%0], [%1], 16;" :: "r"(dst), "l"(src) : "memory")
#define CP_COMMIT() asm volatile("cp.async.commit_group;" ::: "memory")
#define CP_WAIT1()  asm volatile("cp.async.wait_group 1;" ::: "memory")

__device__ __forceinline__ void ldsm4(uint32_t* r, uint32_t a) {
    asm volatile("ldmatrix.sync.aligned.m8n8.x4.shared.b16 {%0,%1,%2,%3}, [%4];"
        : "=r"(r[0]), "=r"(r[1]), "=r"(r[2]), "=r"(r[3]) : "r"(a));
}
__device__ __forceinline__ void ldsm4t(uint32_t* r, uint32_t a) {
    asm volatile("ldmatrix.sync.aligned.m8n8.x4.trans.shared.b16 {%0,%1,%2,%3}, [%4];"
        : "=r"(r[0]), "=r"(r[1]), "=r"(r[2]), "=r"(r[3]) : "r"(a));
}
__device__ __forceinline__ void mma16816(float* d, const uint32_t* a, uint32_t b0, uint32_t b1) {
    asm volatile("mma.sync.aligned.m16n8k16.row.col.f32.bf16.bf16.f32 "
        "{%0,%1,%2,%3}, {%4,%5,%6,%7}, {%8,%9}, {%0,%1,%2,%3};"
        : "+f"(d[0]), "+f"(d[1]), "+f"(d[2]), "+f"(d[3])
        : "r"(a[0]), "r"(a[1]), "r"(a[2]), "r"(a[3]), "r"(b0), "r"(b1));
}
__device__ __forceinline__ uint32_t packbf(float hi, float lo) {
    uint32_t r;
    asm("cvt.rn.bf16x2.f32 %0, %1, %2;" : "=r"(r) : "f"(hi), "f"(lo));
    return r;
}

// ---------------------------------------------------------------------------
// Projection v2: thread owns 4 channels x 8 n. W staged in smem in 32-i
// chunks (transposed Wc[32][260]); x tile staged once. ~48B LDS per i-step.
// ---------------------------------------------------------------------------
#define WPAD 260
#define PROJ_SMEM ((CIN * 32 + 32 * WPAD) * 4)

__global__ __launch_bounds__(256) void proj_kernel(
    const float* __restrict__ x, const float* __restrict__ Wq,
    const float* __restrict__ Wk, const float* __restrict__ Wv)
{
    extern __shared__ float ps[];
    float* xs = ps;              // [128][32]
    float* Wc = ps + CIN * 32;   // [32][260]

    int b  = blockIdx.x >> 7;
    int n0 = (blockIdx.x & 127) << 5;
    int tid = threadIdx.x;
    int cg = tid >> 2, ng = tid & 3;
    int c0 = cg * 4;

    for (int idx = tid; idx < CIN * 32; idx += 256) {
        int i = idx >> 5, j = idx & 31;
        xs[i * 32 + j] = x[(b * CIN + i) * NSEQ + n0 + j];
    }

    float acc[4][8];
#pragma unroll
    for (int k = 0; k < 4; k++)
#pragma unroll
        for (int j = 0; j < 8; j++) acc[k][j] = 0.f;

    for (int chunk = 0; chunk < 4; chunk++) {
        __syncthreads();
        for (int idx = tid; idx < 8192; idx += 256) {
            int c = idx >> 5, q = idx & 31;
            const float* wr = (c < 64) ? (Wq + c * CIN)
                            : (c < 128) ? (Wk + (c - 64) * CIN)
                                        : (Wv + (c - 128) * CIN);
            Wc[q * WPAD + c] = wr[chunk * 32 + q];
        }
        __syncthreads();
#pragma unroll
        for (int q = 0; q < 32; q++) {
            int i = chunk * 32 + q;
            float4 wv = *(const float4*)&Wc[q * WPAD + c0];
            float4 xa = *(const float4*)&xs[i * 32 + ng * 8];
            float4 xb = *(const float4*)&xs[i * 32 + ng * 8 + 4];
            float xv[8] = { xa.x, xa.y, xa.z, xa.w, xb.x, xb.y, xb.z, xb.w };
            float wk[4] = { wv.x, wv.y, wv.z, wv.w };
#pragma unroll
            for (int k = 0; k < 4; k++)
#pragma unroll
                for (int j = 0; j < 8; j++) acc[k][j] += wk[k] * xv[j];
        }
    }

    // stores: 4 consecutive channels -> two bf16x2 words (8B) per n, hi & lo
#pragma unroll
    for (int j = 0; j < 8; j++) {
        int n = n0 + ng * 8 + j;
        float a0 = acc[0][j], a1 = acc[1][j], a2 = acc[2][j], a3 = acc[3][j];
        uint32_t h01 = packbf(a1, a0), h23 = packbf(a3, a2);
        float r0 = a0 - __uint_as_float(h01 << 16);
        float r1 = a1 - __uint_as_float(h01 & 0xffff0000u);
        float r2 = a2 - __uint_as_float(h23 << 16);
        float r3 = a3 - __uint_as_float(h23 & 0xffff0000u);
        uint32_t l01 = packbf(r1, r0), l23 = packbf(r3, r2);
        if (c0 < 128) {
            __nv_bfloat16* dh = (c0 < 64) ? g_Qh : g_Kh;
            __nv_bfloat16* dl = (c0 < 64) ? g_Ql : g_Kl;
            size_t o = ((size_t)(b * NSEQ + n)) * DK + (c0 & 63);
            *(uint2*)(dh + o) = make_uint2(h01, h23);
            *(uint2*)(dl + o) = make_uint2(l01, l23);
        } else {
            size_t o = ((size_t)(b * NSEQ + n)) * DV + (c0 - 128);
            *(uint2*)(g_Vh + o) = make_uint2(h01, h23);
            *(uint2*)(g_Vl + o) = make_uint2(l01, l23);
        }
    }
}

// ---------------------------------------------------------------------------
// FA2 attention: BM=64 (4 warps x 16 rows), BN=64, double-buffered cp.async,
// 2 CTAs/SM. smem: QH 0 | QL 8K | buf0 16K | buf1 64K  (buf: KH,KL,VH,VL)
// ---------------------------------------------------------------------------
#define SM_Q   0
#define SM_BUF 16384
#define BUFSZ  49152
#define B_KH   0
#define B_KL   8192
#define B_VH   16384
#define B_VL   32768
#define SMEM_BYTES (16384 + 2 * BUFSZ)

__global__ __launch_bounds__(128, 2) void attn_kernel(float* __restrict__ out)
{
    extern __shared__ char raw[];
    uint32_t sb = smem_u32(raw);

    int tid = threadIdx.x, w = tid >> 5, lane = tid & 31;
    int b  = blockIdx.x >> 6;
    int q0 = (blockIdx.x & 63) << 6;

    uint32_t xm = (lane & 7) << 4;
    uint32_t qrow = 16 * w + (lane & 15);
    uint32_t qc   = (lane >> 4) << 4;
    uint32_t aQH = sb + SM_Q + qrow * 128;
    uint32_t aQL = aQH + 8192;
    uint32_t krow = (lane & 7) + ((lane >> 4) << 3);
    uint32_t kc   = ((lane >> 3) & 1) << 4;
    uint32_t vrow = (lane & 7) + (((lane >> 3) & 1) << 3);
    uint32_t vc   = (lane >> 4) << 4;

    const char* gQh = (const char*)g_Qh + ((size_t)(b * NSEQ + q0)) * 128;
    const char* gQl = (const char*)g_Ql + ((size_t)(b * NSEQ + q0)) * 128;
    const char* gKh = (const char*)g_Kh + ((size_t)b * NSEQ) * 128;
    const char* gKl = (const char*)g_Kl + ((size_t)b * NSEQ) * 128;
    const char* gVh = (const char*)g_Vh + ((size_t)b * NSEQ) * 256;
    const char* gVl = (const char*)g_Vl + ((size_t)b * NSEQ) * 256;

    // Q tile + tile0 (group 0), tile1 (group 1)
    for (int i = tid; i < 512; i += 128) {
        uint32_t r = i >> 3, c = i & 7;
        uint32_t so = r * 128 + ((c ^ (r & 7)) << 4);
        size_t go = (size_t)r * 128 + c * 16;
        CP_ASYNC16(sb + SM_Q + so,        gQh + go);
        CP_ASYNC16(sb + SM_Q + 8192 + so, gQl + go);
    }
#define LOAD_TILE(t, base) do {                                              \
    const char* _kh = gKh + (size_t)(t) * (BN * 128);                        \
    const char* _kl = gKl + (size_t)(t) * (BN * 128);                        \
    const char* _vh = gVh + (size_t)(t) * (BN * 256);                        \
    const char* _vl = gVl + (size_t)(t) * (BN * 256);                        \
    for (int i = tid; i < 512; i += 128) {                                   \
        uint32_t r = i >> 3, c = i & 7;                                      \
        uint32_t so = r * 128 + ((c ^ (r & 7)) << 4);                        \
        size_t ko = (size_t)r * 128 + c * 16;                                \
        size_t vo = (size_t)r * 256 + c * 16;                                \
        CP_ASYNC16((base) + B_KH + so, _kh + ko);                            \
        CP_ASYNC16((base) + B_KL + so, _kl + ko);                            \
        CP_ASYNC16((base) + B_VH + so,        _vh + vo);                     \
        CP_ASYNC16((base) + B_VH + 8192 + so, _vh + vo + 128);               \
        CP_ASYNC16((base) + B_VL + so,        _vl + vo);                     \
        CP_ASYNC16((base) + B_VL + 8192 + so, _vl + vo + 128);               \
    }                                                                        \
} while (0)
    LOAD_TILE(0, sb + SM_BUF);
    CP_COMMIT();
    LOAD_TILE(1, sb + SM_BUF + BUFSZ);
    CP_COMMIT();

    uint32_t QHf[4][4], QLf[4][4];
    float Of[16][4];
#pragma unroll
    for (int t = 0; t < 16; t++)
#pragma unroll
        for (int j = 0; j < 4; j++) Of[t][j] = 0.f;
    float m0 = -1e30f, m1 = -1e30f, l0 = 0.f, l1 = 0.f;

    for (int kt = 0; kt < NITER; kt++) {
        CP_WAIT1();
        __syncthreads();
        uint32_t sbuf = sb + SM_BUF + (uint32_t)(kt & 1) * BUFSZ;
        uint32_t aKH = sbuf + B_KH + krow * 128;
        uint32_t aKL = sbuf + B_KL + krow * 128;
        uint32_t aVH = sbuf + B_VH + vrow * 128;
        uint32_t aVL = sbuf + B_VL + vrow * 128;

        if (kt == 0) {
#pragma unroll
            for (int ks = 0; ks < 4; ks++) {
                uint32_t cc = (ks * 32 + qc) ^ xm;
                ldsm4(QHf[ks], aQH + cc);
                ldsm4(QLf[ks], aQL + cc);
            }
        }

        // ---- GEMM1: S = Qh*Kh + Ql*Kh + Qh*Kl ----
        float Sx[8][4];
#pragma unroll
        for (int t = 0; t < 8; t++)
#pragma unroll
            for (int j = 0; j < 4; j++) Sx[t][j] = 0.f;
#pragma unroll
        for (int tp = 0; tp < 4; tp++) {
#pragma unroll
            for (int ks = 0; ks < 4; ks++) {
                uint32_t cc = (ks * 32 + kc) ^ xm;
                uint32_t kh[4], kl[4];
                ldsm4(kh, aKH + tp * 2048 + cc);
                ldsm4(kl, aKL + tp * 2048 + cc);
                mma16816(Sx[2 * tp],     QHf[ks], kh[0], kh[1]);
                mma16816(Sx[2 * tp + 1], QHf[ks], kh[2], kh[3]);
                mma16816(Sx[2 * tp],     QLf[ks], kh[0], kh[1]);
                mma16816(Sx[2 * tp + 1], QLf[ks], kh[2], kh[3]);
                mma16816(Sx[2 * tp],     QHf[ks], kl[0], kl[1]);
                mma16816(Sx[2 * tp + 1], QHf[ks], kl[2], kl[3]);
            }
        }

        // ---- online softmax (registers only) ----
        float mt0 = -1e30f, mt1 = -1e30f;
#pragma unroll
        for (int t = 0; t < 8; t++) {
            mt0 = fmaxf(mt0, fmaxf(Sx[t][0], Sx[t][1]));
            mt1 = fmaxf(mt1, fmaxf(Sx[t][2], Sx[t][3]));
        }
        mt0 = fmaxf(mt0, __shfl_xor_sync(0xffffffffu, mt0, 1));
        mt0 = fmaxf(mt0, __shfl_xor_sync(0xffffffffu, mt0, 2));
        mt1 = fmaxf(mt1, __shfl_xor_sync(0xffffffffu, mt1, 1));
        mt1 = fmaxf(mt1, __shfl_xor_sync(0xffffffffu, mt1, 2));
        float n0v = fmaxf(m0, mt0), n1v = fmaxf(m1, mt1);
        float c0 = __expf(m0 - n0v), c1 = __expf(m1 - n1v);
        m0 = n0v; m1 = n1v;
        l0 *= c0; l1 *= c1;
#pragma unroll
        for (int t = 0; t < 16; t++) {
            Of[t][0] *= c0; Of[t][1] *= c0;
            Of[t][2] *= c1; Of[t][3] *= c1;
        }
        uint32_t PH[8][2], PL[8][2];
#pragma unroll
        for (int t = 0; t < 8; t++) {
            float p0 = __expf(Sx[t][0] - m0), p1 = __expf(Sx[t][1] - m0);
            float p2 = __expf(Sx[t][2] - m1), p3 = __expf(Sx[t][3] - m1);
            l0 += p0 + p1; l1 += p2 + p3;
            uint32_t h01 = packbf(p1, p0);
            uint32_t h23 = packbf(p3, p2);
            PH[t][0] = h01; PH[t][1] = h23;
            float r0 = p0 - __uint_as_float(h01 << 16);
            float r1 = p1 - __uint_as_float(h01 & 0xffff0000u);
            float r2 = p2 - __uint_as_float(h23 << 16);
            float r3 = p3 - __uint_as_float(h23 & 0xffff0000u);
            PL[t][0] = packbf(r1, r0);
            PL[t][1] = packbf(r3, r2);
        }

        // ---- GEMM2: O += Ph*Vh + Pl*Vh + Ph*Vl ----
#pragma unroll
        for (int hp = 0; hp < 2; hp++) {
#pragma unroll
            for (int tp2 = 0; tp2 < 4; tp2++) {
#pragma unroll
                for (int ks = 0; ks < 4; ks++) {
                    uint32_t cc = (tp2 * 32 + vc) ^ xm;
                    uint32_t vh[4], vl[4];
                    ldsm4t(vh, aVH + hp * 8192 + ks * 2048 + cc);
                    ldsm4t(vl, aVL + hp * 8192 + ks * 2048 + cc);
                    int t0 = hp * 8 + tp2 * 2, t1 = t0 + 1;
                    uint32_t aH[4] = { PH[2 * ks][0], PH[2 * ks][1], PH[2 * ks + 1][0], PH[2 * ks + 1][1] };
                    uint32_t aL[4] = { PL[2 * ks][0], PL[2 * ks][1], PL[2 * ks + 1][0], PL[2 * ks + 1][1] };
                    mma16816(Of[t0], aH, vh[0], vh[1]);
                    mma16816(Of[t1], aH, vh[2], vh[3]);
                    mma16816(Of[t0], aL, vh[0], vh[1]);
                    mma16816(Of[t1], aL, vh[2], vh[3]);
                    mma16816(Of[t0], aH, vl[0], vl[1]);
                    mma16816(Of[t1], aH, vl[2], vl[3]);
                }
            }
        }

        __syncthreads();
        if (kt + 2 < NITER) {
            LOAD_TILE(kt + 2, sb + SM_BUF + (uint32_t)(kt & 1) * BUFSZ);
        }
        CP_COMMIT();
    }

    // ---- epilogue: normalize, transpose via smem, coalesced store ----
    l0 += __shfl_xor_sync(0xffffffffu, l0, 1);
    l0 += __shfl_xor_sync(0xffffffffu, l0, 2);
    l1 += __shfl_xor_sync(0xffffffffu, l1, 1);
    l1 += __shfl_xor_sync(0xffffffffu, l1, 2);
    float inv0 = 1.f / l0, inv1 = 1.f / l1;

    __syncthreads();
    float* Os = (float*)raw;   // [64][129]
    int rowA = 16 * w + (lane >> 2);
    int rowB = rowA + 8;
#pragma unroll
    for (int t = 0; t < 16; t++) {
        int ch = t * 8 + (lane & 3) * 2;
        Os[rowA * 129 + ch]     = Of[t][0] * inv0;
        Os[rowA * 129 + ch + 1] = Of[t][1] * inv0;
        Os[rowB * 129 + ch]     = Of[t][2] * inv1;
        Os[rowB * 129 + ch + 1] = Of[t][3] * inv1;
    }
    __syncthreads();

    int nn = tid & 63;
    int hf = tid >> 6;
    const float* Or = Os + nn * 129 + hf * 64;
    float* op = out + ((size_t)b * DV + hf * 64) * NSEQ + q0 + nn;
#pragma unroll 8
    for (int c2 = 0; c2 < 64; c2++) op[(size_t)c2 * NSEQ] = Or[c2];
}

// ---------------------------------------------------------------------------
extern "C" void kernel_launch(void* const* d_in, const int* in_sizes, int n_in,
                              void* d_out, int out_size)
{
    const float* x  = (const float*)d_in[0];
    const float* Wq = (const float*)d_in[1];
    const float* Wk = (const float*)d_in[2];
    const float* Wv = (const float*)d_in[3];
    float* out = (float*)d_out;

    cudaFuncSetAttribute(attn_kernel, cudaFuncAttributeMaxDynamicSharedMemorySize,
                         SMEM_BYTES);
    cudaFuncSetAttribute(proj_kernel, cudaFuncAttributeMaxDynamicSharedMemorySize,
                         PROJ_SMEM);

    proj_kernel<<<BATCH * (NSEQ / 32), 256, PROJ_SMEM>>>(x, Wq, Wk, Wv);
    attn_kernel<<<BATCH * (NSEQ / BM), 128, SMEM_BYTES>>>(out);
}